// round 10
// baseline (speedup 1.0000x reference)
#include <cuda_runtime.h>
#include <cuda_bf16.h>
#include <cstdint>
#include <cstddef>

// Problem constants: B=4, S=4096, D=512
#define ROWS_TOTAL 16384
#define DIMD 512
#define CCHUNK 256
#define NCHUNKS 64
#define CHUNKS_PER_BATCH 16

#define NE  ((size_t)ROWS_TOTAL * DIMD)             // 8,388,608
#define NQKV ((size_t)ROWS_TOTAL * 3 * DIMD)        // 25,165,824
#define STN ((size_t)NCHUNKS * DIMD * DIMD)         // 16,777,216
#define SCN ((size_t)NCHUNKS * CCHUNK * CCHUNK)     // 4,194,304

#define SSQ ((long)CCHUNK * CCHUNK)                 // 65536
#define CHQ ((long)CCHUNK * 3 * DIMD)               // 393216
#define CHY ((long)CCHUNK * DIMD)                   // 131072
#define STQ ((long)DIMD * DIMD)                     // 262144

typedef __nv_bfloat16 bf;

// ---------------------------------------------------------------------------
// Scratch (static device globals)
// ---------------------------------------------------------------------------
__device__ __align__(16) bf g_xh[NE], g_xl[NE];
__device__ __align__(16) bf g_qkvh[NQKV], g_qkvl[NQKV];     // [16384][1536]
__device__ __align__(16) bf g_yh[NE], g_yl[NE];
__device__ __align__(16) bf g_kth[NE], g_ktl[NE];           // [512][16384]
__device__ __align__(16) bf g_vth[NE], g_vtl[NE];
__device__ __align__(16) bf g_wth[(size_t)4 * DIMD * DIMD]; // [4][512 n][512 k] = W^T
__device__ __align__(16) bf g_wtl[(size_t)4 * DIMD * DIMD];
__device__ __align__(16) bf g_ph[STN], g_pl[STN];
__device__ __align__(16) bf g_sch[SCN], g_scl[SCN];
__device__ __align__(16) float g_st[STN];

// ---------------------------------------------------------------------------
// helpers
// ---------------------------------------------------------------------------
__device__ __forceinline__ uint32_t smem_u32(const void* p) {
    uint32_t a;
    asm("{ .reg .u64 t; cvta.to.shared.u64 t, %1; cvt.u32.u64 %0, t; }" : "=r"(a) : "l"(p));
    return a;
}
__device__ __forceinline__ void cp16(uint32_t dst, const void* src) {
    asm volatile("cp.async.cg.shared.global [%0], [%1], 16;" :: "r"(dst), "l"(src));
}
#define CP_COMMIT() asm volatile("cp.async.commit_group;" ::: "memory")
template <int N> __device__ __forceinline__ void cp_wait() {
    asm volatile("cp.async.wait_group %0;" :: "n"(N) : "memory");
}
__device__ __forceinline__ void ldm4(uint32_t* r, uint32_t addr) {
    asm volatile("ldmatrix.sync.aligned.m8n8.x4.shared.b16 {%0,%1,%2,%3}, [%4];"
                 : "=r"(r[0]), "=r"(r[1]), "=r"(r[2]), "=r"(r[3]) : "r"(addr));
}
__device__ __forceinline__ void mma16816(float* d, const uint32_t* a, uint32_t b0, uint32_t b1) {
    asm volatile("mma.sync.aligned.m16n8k16.row.col.f32.bf16.bf16.f32 "
                 "{%0,%1,%2,%3},{%4,%5,%6,%7},{%8,%9},{%0,%1,%2,%3};"
                 : "+f"(d[0]), "+f"(d[1]), "+f"(d[2]), "+f"(d[3])
                 : "r"(a[0]), "r"(a[1]), "r"(a[2]), "r"(a[3]), "r"(b0), "r"(b1));
}
__device__ __forceinline__ void split1(float v, uint16_t& h, uint16_t& l) {
    __nv_bfloat16 hb = __float2bfloat16(v);
    __nv_bfloat16 lb = __float2bfloat16(v - __bfloat162float(hb));
    h = __bfloat16_as_ushort(hb);
    l = __bfloat16_as_ushort(lb);
}
__device__ __forceinline__ void split2(float v0, float v1, uint32_t& hi, uint32_t& lo) {
    uint16_t h0, l0, h1, l1;
    split1(v0, h0, l0); split1(v1, h1, l1);
    hi = (uint32_t)h0 | ((uint32_t)h1 << 16);
    lo = (uint32_t)l0 | ((uint32_t)l1 << 16);
}

// ---------------------------------------------------------------------------
// shared GEMM core: CTA tile 128x128, 8 warps (2m x 4n), warp tile 64x32.
// C = sum_k A1*B1^T (+ sum_k A2*B2^T if K2>0), split-bf16 3-term, fp32 accum.
// 3-stage cp.async pipeline, one __syncthreads per 32-k chunk.
// MODE 0: C f32; MODE 1: split planes; MODE 2: split planes + causal mask.
// ---------------------------------------------------------------------------
#define STAGE_BYTES 32768
#define GSMEM (3 * STAGE_BYTES)   // 96 KB -> 2 CTAs/SM

template <int MODE>
__device__ __forceinline__ void gemm_core(
    const bf* __restrict__ A1h, const bf* __restrict__ A1l, long sA1, int lda1,
    const bf* __restrict__ B1h, const bf* __restrict__ B1l, long sB1, int ldb1, int K1,
    const bf* __restrict__ A2h, const bf* __restrict__ A2l, long sA2, int lda2,
    const bf* __restrict__ B2h, const bf* __restrict__ B2l, long sB2, int ldb2, int K2,
    void* __restrict__ Chv, void* __restrict__ Clv, long sC, int ldc,
    uint32_t sm, int bm, int bn, long z)
{
    const int tid = threadIdx.x, lane = tid & 31, wid = tid >> 5;
    const int wm = wid & 1, wn = wid >> 1;      // 2 x 4

    float acc[4][4][4];
#pragma unroll
    for (int i = 0; i < 4; i++)
#pragma unroll
        for (int j = 0; j < 4; j++)
#pragma unroll
            for (int q = 0; q < 4; q++) acc[i][j][q] = 0.0f;

    auto load = [&](const bf* Ah, const bf* Al, int lda,
                    const bf* Bh, const bf* Bl, int ldb, int c, int buf) {
        const int k0 = c * 32;
        const uint32_t sb = sm + buf * STAGE_BYTES;
#pragma unroll
        for (int i = 0; i < 4; i++) {
            int e = tid + 256 * i;              // A: 1024 cp16
            int row = e >> 3, ch = e & 7;
            int kc = k0 + (ch & 3) * 8;
            const bf* src = (ch < 4 ? Ah : Al) + (long)row * lda + kc;
            uint32_t sw = (uint32_t)(row * 128 + ((ch ^ (row & 7)) << 4));
            cp16(sb + sw, src);
        }
#pragma unroll
        for (int i = 0; i < 4; i++) {
            int e = tid + 256 * i;              // B: 1024 cp16
            int row = e >> 3, ch = e & 7;
            int kc = k0 + (ch & 3) * 8;
            const bf* src = (ch < 4 ? Bh : Bl) + (long)row * ldb + kc;
            uint32_t sw = (uint32_t)(row * 128 + ((ch ^ (row & 7)) << 4));
            cp16(sb + 16384 + sw, src);
        }
    };

    auto compute = [&](int buf) {
        const uint32_t ba = sm + buf * STAGE_BYTES;
        const uint32_t bb = ba + 16384;
#pragma unroll
        for (int kh2 = 0; kh2 < 2; kh2++) {
            uint32_t ahf[4][4], alf[4][4];
#pragma unroll
            for (int mf = 0; mf < 4; mf++) {
                int row = wm * 64 + mf * 16 + (lane & 7) + ((lane >> 3) & 1) * 8;
                int ch = kh2 * 2 + (lane >> 4);
                ldm4(ahf[mf], ba + row * 128 + ((ch ^ (row & 7)) << 4));
                ldm4(alf[mf], ba + row * 128 + (((ch + 4) ^ (row & 7)) << 4));
            }
#pragma unroll
            for (int bi = 0; bi < 2; bi++) {
                uint32_t bhf[4], blf[4];
                int row = wn * 32 + bi * 16 + (lane & 7) + (lane >> 4) * 8;
                int ch = kh2 * 2 + ((lane >> 3) & 1);
                ldm4(bhf, bb + row * 128 + ((ch ^ (row & 7)) << 4));
                ldm4(blf, bb + row * 128 + (((ch + 4) ^ (row & 7)) << 4));
#pragma unroll
                for (int mf = 0; mf < 4; mf++) {
#pragma unroll
                    for (int half = 0; half < 2; half++) {
                        int nf = bi * 2 + half;
                        mma16816(acc[mf][nf], ahf[mf], bhf[2 * half], bhf[2 * half + 1]);
                        mma16816(acc[mf][nf], ahf[mf], blf[2 * half], blf[2 * half + 1]);
                        mma16816(acc[mf][nf], alf[mf], bhf[2 * half], bhf[2 * half + 1]);
                    }
                }
            }
        }
    };

    auto run = [&](const bf* Ahp, const bf* Alp, long sA, int lda,
                   const bf* Bhp, const bf* Blp, long sB, int ldb, int K, bool first) {
        const bf* Ah = Ahp + z * sA + (long)bm * lda;
        const bf* Al = Alp + z * sA + (long)bm * lda;
        const bf* Bh = Bhp + z * sB + (long)bn * ldb;
        const bf* Bl = Blp + z * sB + (long)bn * ldb;
        const int nch = K >> 5;
        if (!first) __syncthreads();    // protect stage buffers across runs
        load(Ah, Al, lda, Bh, Bl, ldb, 0, 0); CP_COMMIT();
        if (nch > 1) { load(Ah, Al, lda, Bh, Bl, ldb, 1, 1); CP_COMMIT(); }
        for (int c = 0; c < nch; c++) {
            if (c + 1 < nch) cp_wait<1>(); else cp_wait<0>();
            __syncthreads();
            if (c + 2 < nch) {
                load(Ah, Al, lda, Bh, Bl, ldb, c + 2, (c + 2) % 3);
                CP_COMMIT();
            }
            compute(c % 3);
        }
    };

    run(A1h, A1l, sA1, lda1, B1h, B1l, sB1, ldb1, K1, true);
    if (K2 > 0) run(A2h, A2l, sA2, lda2, B2h, B2l, sB2, ldb2, K2, false);

    // epilogue
    const long rbase = z * sC;
#pragma unroll
    for (int mf = 0; mf < 4; mf++) {
#pragma unroll
        for (int nf = 0; nf < 4; nf++) {
            float* d = acc[mf][nf];
            int r = bm + wm * 64 + mf * 16 + (lane >> 2);
            int c = bn + wn * 32 + nf * 8 + (lane & 3) * 2;
            long i0 = rbase + (long)r * ldc + c;
            long i1 = i0 + 8L * ldc;
            if (MODE == 0) {
                float* C = (float*)Chv;
                *(float2*)(C + i0) = make_float2(d[0], d[1]);
                *(float2*)(C + i1) = make_float2(d[2], d[3]);
            } else {
                float v0 = d[0], v1 = d[1], v2 = d[2], v3 = d[3];
                if (MODE == 2) {
                    if (c     > r)     v0 = 0.0f;
                    if (c + 1 > r)     v1 = 0.0f;
                    if (c     > r + 8) v2 = 0.0f;
                    if (c + 1 > r + 8) v3 = 0.0f;
                }
                uint32_t hi0, lo0, hi1, lo1;
                split2(v0, v1, hi0, lo0);
                split2(v2, v3, hi1, lo1);
                bf* Ch = (bf*)Chv; bf* Cl = (bf*)Clv;
                *(uint32_t*)(Ch + i0) = hi0;
                *(uint32_t*)(Cl + i0) = lo0;
                *(uint32_t*)(Ch + i1) = hi1;
                *(uint32_t*)(Cl + i1) = lo1;
            }
        }
    }
}

template <int MODE>
__global__ __launch_bounds__(256, 2)
void gemm2(const bf* __restrict__ A1h, const bf* __restrict__ A1l, long sA1, int lda1,
           const bf* __restrict__ B1h, const bf* __restrict__ B1l, long sB1, int ldb1, int K1,
           const bf* __restrict__ A2h, const bf* __restrict__ A2l, long sA2, int lda2,
           const bf* __restrict__ B2h, const bf* __restrict__ B2l, long sB2, int ldb2, int K2,
           void* __restrict__ Chv, void* __restrict__ Clv, long sC, int ldc)
{
    extern __shared__ __align__(128) char dsm[];
    gemm_core<MODE>(A1h, A1l, sA1, lda1, B1h, B1l, sB1, ldb1, K1,
                    A2h, A2l, sA2, lda2, B2h, B2l, sB2, ldb2, K2,
                    Chv, Clv, sC, ldc,
                    smem_u32(dsm), blockIdx.y * 128, blockIdx.x * 128, blockIdx.z);
}

// ---------------------------------------------------------------------------
// fused scores GEMM (ids 0..255) + k/v transpose (ids 256..16639)
// ---------------------------------------------------------------------------
__global__ __launch_bounds__(256, 2)
void fused_su(const bf* __restrict__ qkvh, const bf* __restrict__ qkvl,
              bf* __restrict__ sch, bf* __restrict__ scl,
              bf* __restrict__ kth, bf* __restrict__ ktl,
              bf* __restrict__ vth, bf* __restrict__ vtl)
{
    extern __shared__ __align__(128) char dsm[];
    const int id = blockIdx.x;
    const int tid = threadIdx.x;

    if (id < 256) {
        // scores block: grid decode (x=n, y=m, z=chunk)
        const int x = id & 1, y = (id >> 1) & 1;
        const long z = id >> 2;
        const int bm = y * 128, bn = x * 128;
        if (bn > bm) {
            // fully above diagonal -> zeros, no compute
            bf* Ch = sch + z * SSQ;
            bf* Cl = scl + z * SSQ;
            const uint4 zz = make_uint4(0u, 0u, 0u, 0u);
            for (int i = tid; i < 2048; i += 256) {
                int r = i >> 4, q = i & 15;
                long off = (long)r * CCHUNK + 128 + q * 8;
                *(uint4*)(Ch + off) = zz;
                *(uint4*)(Cl + off) = zz;
            }
            return;
        }
        gemm_core<2>(qkvh, qkvl, CHQ, 3 * DIMD,
                     qkvh + DIMD, qkvl + DIMD, CHQ, 3 * DIMD, DIMD,
                     nullptr, nullptr, 0, 0, nullptr, nullptr, 0, 0, 0,
                     sch, scl, SSQ, CCHUNK,
                     smem_u32(dsm), bm, bn, z);
    } else {
        // transpose tile: decode (x 0..15, y 0..511, zc 0..1)
        const int t = id - 256;
        const int x = t & 15, y = (t >> 4) & 511, zc = t >> 13;
        bf (*sh)[33] = (bf(*)[33])dsm;
        bf (*sl)[33] = (bf(*)[33])(dsm + 32 * 33 * sizeof(bf));
        const int lds = 3 * DIMD;
        const bf* ih = qkvh + (zc + 1) * DIMD;
        const bf* il = qkvl + (zc + 1) * DIMD;
        bf* oh = zc ? vth : kth;
        bf* ol = zc ? vtl : ktl;
        int c0 = x * 32, r0 = y * 32;
        int tx = tid & 31, ty = tid >> 5;
#pragma unroll
        for (int i = 0; i < 4; i++) {
            long src = (long)(r0 + ty + 8 * i) * lds + c0 + tx;
            sh[ty + 8 * i][tx] = ih[src];
            sl[ty + 8 * i][tx] = il[src];
        }
        __syncthreads();
#pragma unroll
        for (int i = 0; i < 4; i++) {
            long dst = (long)(c0 + ty + 8 * i) * ROWS_TOTAL + r0 + tx;
            oh[dst] = sh[tx][ty + 8 * i];
            ol[dst] = sl[tx][ty + 8 * i];
        }
    }
}

// ---------------------------------------------------------------------------
// fused prep: weight transpose+split (ids 0..1023) + x pack (ids 1024..5119)
// ---------------------------------------------------------------------------
__global__ __launch_bounds__(256)
void prep(const float4* __restrict__ x4, bf* __restrict__ xh, bf* __restrict__ xl, int n4,
          const float* __restrict__ w0, const float* __restrict__ w1,
          const float* __restrict__ w2, const float* __restrict__ w3,
          bf* __restrict__ th, bf* __restrict__ tl)
{
    const int id = blockIdx.x;
    if (id < 1024) {
        const float* Ws[4] = {w0, w1, w2, w3};
        const int wx = id & 15, wy = (id >> 4) & 15, wz = id >> 8;
        const float* W = Ws[wz];
        __shared__ float s[32][33];
        int n0 = wx * 32, k0 = wy * 32;
        int tx = threadIdx.x & 31, ty = threadIdx.x >> 5;
#pragma unroll
        for (int i = 0; i < 4; i++)
            s[ty + 8 * i][tx] = W[(long)(k0 + ty + 8 * i) * DIMD + n0 + tx];
        __syncthreads();
#pragma unroll
        for (int i = 0; i < 4; i++) {
            float v = s[tx][ty + 8 * i];
            uint16_t h, l;
            split1(v, h, l);
            size_t o = (size_t)wz * DIMD * DIMD + (size_t)(n0 + ty + 8 * i) * DIMD + k0 + tx;
            ((uint16_t*)th)[o] = h;
            ((uint16_t*)tl)[o] = l;
        }
    } else {
        const int idp = id - 1024;
        for (int i = idp * 256 + threadIdx.x; i < n4; i += 4096 * 256) {
            float4 f = x4[i];
            uint32_t h0, l0, h1, l1;
            split2(f.x, f.y, h0, l0);
            split2(f.z, f.w, h1, l1);
            *(uint2*)(xh + (size_t)i * 4) = make_uint2(h0, h1);
            *(uint2*)(xl + (size_t)i * 4) = make_uint2(l0, l1);
        }
    }
}

__global__ __launch_bounds__(256)
void prefix_split(const float* __restrict__ st, bf* __restrict__ ph, bf* __restrict__ pl)
{
    const int e = blockIdx.x * 256 + threadIdx.x;
    const int b = blockIdx.y;
    float run = 0.0f;
    for (int c = 0; c < CHUNKS_PER_BATCH; c++) {
        size_t idx = ((size_t)(b * CHUNKS_PER_BATCH + c)) * ((size_t)DIMD * DIMD) + e;
        uint16_t h, l;
        split1(run, h, l);
        ((uint16_t*)ph)[idx] = h;
        ((uint16_t*)pl)[idx] = l;
        run += st[idx];
    }
}

// ---------------------------------------------------------------------------
// launcher
// ---------------------------------------------------------------------------
extern "C" void kernel_launch(void* const* d_in, const int* in_sizes, int n_in,
                              void* d_out, int out_size)
{
    int xi = 0;
    for (int i = 0; i < n_in; i++)
        if (in_sizes[i] == (int)(ROWS_TOTAL * DIMD)) { xi = i; break; }
    const float* W[4]; int wi = 0;
    for (int i = 0; i < n_in && wi < 4; i++) { if (i == xi) continue; W[wi++] = (const float*)d_in[i]; }
    const float* x = (const float*)d_in[xi];

    bf *xh, *xl, *qkvh, *qkvl, *yh, *yl, *kth, *ktl, *vth, *vtl, *wth, *wtl, *ph, *pl, *sch, *scl;
    float *st;
    cudaGetSymbolAddress((void**)&xh, g_xh);     cudaGetSymbolAddress((void**)&xl, g_xl);
    cudaGetSymbolAddress((void**)&qkvh, g_qkvh); cudaGetSymbolAddress((void**)&qkvl, g_qkvl);
    cudaGetSymbolAddress((void**)&yh, g_yh);     cudaGetSymbolAddress((void**)&yl, g_yl);
    cudaGetSymbolAddress((void**)&kth, g_kth);   cudaGetSymbolAddress((void**)&ktl, g_ktl);
    cudaGetSymbolAddress((void**)&vth, g_vth);   cudaGetSymbolAddress((void**)&vtl, g_vtl);
    cudaGetSymbolAddress((void**)&wth, g_wth);   cudaGetSymbolAddress((void**)&wtl, g_wtl);
    cudaGetSymbolAddress((void**)&ph, g_ph);     cudaGetSymbolAddress((void**)&pl, g_pl);
    cudaGetSymbolAddress((void**)&sch, g_sch);   cudaGetSymbolAddress((void**)&scl, g_scl);
    cudaGetSymbolAddress((void**)&st, g_st);

    cudaFuncSetAttribute(gemm2<0>, cudaFuncAttributeMaxDynamicSharedMemorySize, GSMEM);
    cudaFuncSetAttribute(gemm2<1>, cudaFuncAttributeMaxDynamicSharedMemorySize, GSMEM);
    cudaFuncSetAttribute(fused_su, cudaFuncAttributeMaxDynamicSharedMemorySize, GSMEM);

    // prep: pack x + transpose/split weights (one launch)
    prep<<<5120, 256>>>((const float4*)x, xh, xl, (int)(NE / 4),
                        W[0], W[1], W[2], W[3], wth, wtl);

    // fused q|k|v projection: [16384,1536] = x @ [Wq|Wk|Wv]
    gemm2<1><<<dim3(12, 128, 1), 256, GSMEM>>>(
        xh, xl, 0, DIMD, wth, wtl, 0, DIMD, DIMD,
        nullptr, nullptr, 0, 0, nullptr, nullptr, 0, 0, 0,
        qkvh, qkvl, 0, 3 * DIMD);

    // fused: intra-chunk masked scores + k^T/v^T transposes (one launch)
    fused_su<<<16640, 256, GSMEM>>>(qkvh, qkvl, sch, scl, kth, ktl, vth, vtl);

    // per-chunk state S_c = V_c^T K_c (f32), M=512, N=512, K=256
    gemm2<0><<<dim3(4, 4, NCHUNKS), 256, GSMEM>>>(
        vth, vtl, CCHUNK, ROWS_TOTAL, kth, ktl, CCHUNK, ROWS_TOTAL, CCHUNK,
        nullptr, nullptr, 0, 0, nullptr, nullptr, 0, 0, 0,
        st, nullptr, STQ, DIMD);

    // exclusive prefix over chunks -> P planes
    prefix_split<<<dim3((unsigned)(STQ / 256), 4), 256>>>(st, ph, pl);

    // fused Y_c = Q_c @ P_c^T + scores_c @ V_c  -> split planes
    gemm2<1><<<dim3(4, 2, NCHUNKS), 256, GSMEM>>>(
        qkvh, qkvl, CHQ, 3 * DIMD, ph, pl, STQ, DIMD, DIMD,
        sch, scl, SSQ, CCHUNK, vth, vtl, CCHUNK, ROWS_TOTAL, CCHUNK,
        yh, yl, CHY, DIMD);

    // out = Y @ Wo (f32)
    gemm2<0><<<dim3(4, 128, 1), 256, GSMEM>>>(
        yh, yl, 0, DIMD, wth + 3 * STQ, wtl + 3 * STQ, 0, DIMD, DIMD,
        nullptr, nullptr, 0, 0, nullptr, nullptr, 0, 0, 0,
        d_out, nullptr, 0, DIMD);
}